// round 15
// baseline (speedup 1.0000x reference)
#include <cuda_runtime.h>
#include <cuda_fp16.h>
#include <math.h>

#define N_NODES 50000
#define N_EDGES 1600000
#define DIM 128
#define NEG_SLOPE 0.01f
#define MAXDEG 128            // Poisson(32) -> P(deg>=128) ~ 0 (11+ sigma); guarded anyway

// ---------------- scratch (static device globals; no allocation) ----------------
__device__ float  g_Wp[DIM * DIM];                     // sigmoid(mask) folded into W
__device__ float  g_w1f[DIM];                          // Wp @ aw1 (score fold, src)
__device__ float  g_w2f[DIM];                          // Wp @ aw2 (score fold, dst)
__device__ float  g_sb[2];                             // b@aw1, b@aw2
__device__ __half g_hh[(size_t)N_NODES * DIM];         // projected features (fp16)
__device__ float  g_ssrc[N_NODES];
__device__ float  g_sdst[N_NODES];
__device__ int    g_deg[N_NODES];
__device__ int2   g_csr[(size_t)N_NODES * MAXDEG];     // padded CSR {src, s_src-bits}

// ---------------- f32x2 packed FMA helpers (sm_103a) ----------------------------
__device__ __forceinline__ unsigned long long pack2(float lo, float hi) {
    unsigned long long r;
    asm("mov.b64 %0,{%1,%2};" : "=l"(r) : "f"(lo), "f"(hi));
    return r;
}
__device__ __forceinline__ void unpack2(unsigned long long v, float& lo, float& hi) {
    asm("mov.b64 {%0,%1},%2;" : "=f"(lo), "=f"(hi) : "l"(v));
}
__device__ __forceinline__ void fma2(unsigned long long& d, unsigned long long a, unsigned long long b) {
    asm("fma.rn.f32x2 %0,%1,%2,%0;" : "+l"(d) : "l"(a), "l"(b));
}

// ---------------- K0: fold sigmoid(mask) into W + zero degree counters ----------
__global__ void prep_kernel(const float* __restrict__ W, const float* __restrict__ mask) {
    int i = blockIdx.x * blockDim.x + threadIdx.x;
    if (i < DIM * DIM) {
        int k = i >> 7;
        float s = 1.f / (1.f + __expf(-mask[k]));
        g_Wp[i] = W[i] * s;
    }
    if (i < N_NODES) g_deg[i] = 0;
}

// ---------------- K1: fold attn_w through Wp (warp per row, 16 blocks) ----------
__global__ __launch_bounds__(256) void fold_kernel(const float* __restrict__ attn_w,
                                                   const float* __restrict__ bias) {
    int gw = blockIdx.x * 8 + (threadIdx.x >> 5);   // 0..127 = row of Wp
    int lane = threadIdx.x & 31;
    float4 v1 = ((const float4*)attn_w)[lane];          // aw1 chunk
    float4 v2 = ((const float4*)attn_w)[32 + lane];     // aw2 chunk
    float4 wv = ((const float4*)&g_Wp[gw * DIM])[lane];
    float p1 = wv.x * v1.x + wv.y * v1.y + wv.z * v1.z + wv.w * v1.w;
    float p2 = wv.x * v2.x + wv.y * v2.y + wv.z * v2.z + wv.w * v2.w;
#pragma unroll
    for (int o = 16; o > 0; o >>= 1) {
        p1 += __shfl_xor_sync(0xffffffffu, p1, o);
        p2 += __shfl_xor_sync(0xffffffffu, p2, o);
    }
    if (lane == 0) { g_w1f[gw] = p1; g_w2f[gw] = p2; }
    // bias dots (block 0, warp 0)
    if (blockIdx.x == 0 && (threadIdx.x >> 5) == 0) {
        float4 bv = ((const float4*)bias)[lane];
        float q1 = bv.x * v1.x + bv.y * v1.y + bv.z * v1.z + bv.w * v1.w;
        float q2 = bv.x * v2.x + bv.y * v2.y + bv.z * v2.z + bv.w * v2.w;
#pragma unroll
        for (int o = 16; o > 0; o >>= 1) {
            q1 += __shfl_xor_sync(0xffffffffu, q1, o);
            q2 += __shfl_xor_sync(0xffffffffu, q2, o);
        }
        if (lane == 0) { g_sb[0] = q1; g_sb[1] = q2; }
    }
}

// ---------------- K2: node scores straight from feat (warp per node) ------------
__global__ void score_kernel(const float* __restrict__ feat, int N) {
    int gw = (blockIdx.x * blockDim.x + threadIdx.x) >> 5;
    int lane = threadIdx.x & 31;
    if (gw >= N) return;
    float4 f4 = ((const float4*)(feat + (size_t)gw * DIM))[lane];
    float4 w1 = ((const float4*)g_w1f)[lane];
    float4 w2 = ((const float4*)g_w2f)[lane];
    float s1 = f4.x * w1.x + f4.y * w1.y + f4.z * w1.z + f4.w * w1.w;
    float s2 = f4.x * w2.x + f4.y * w2.y + f4.z * w2.z + f4.w * w2.w;
#pragma unroll
    for (int o = 16; o > 0; o >>= 1) {
        s1 += __shfl_xor_sync(0xffffffffu, s1, o);
        s2 += __shfl_xor_sync(0xffffffffu, s2, o);
    }
    if (lane == 0) {
        g_ssrc[gw] = s1 + g_sb[0];
        g_sdst[gw] = s2 + g_sb[1];
    }
}

// ---------------- K3: h = feat @ Wp + b (fp16 out) ------------------------------
#define GB_M 64
__global__ __launch_bounds__(128) void gemm_kernel(const float* __restrict__ feat,
                                                   const float* __restrict__ bias, int N) {
    extern __shared__ float sm[];
    float* sFT = sm;              // [128 k][64 m] transposed feat tile (32KB)
    float* sW  = sm + 128 * 64;   // [128 k][128 n] (64KB)
    int tid = threadIdx.x;
    int rb = blockIdx.x * GB_M;

    const float4* Wp4 = (const float4*)g_Wp;
    float4* sW4 = (float4*)sW;
#pragma unroll
    for (int i = 0; i < 32; i++) sW4[tid + i * 128] = Wp4[tid + i * 128];

#pragma unroll
    for (int it = 0; it < 8; it++) {
        int idx = tid + it * 128;
        int m = idx & 63, kq = idx >> 6;
        int row = rb + m;
        float4 v0 = make_float4(0.f, 0.f, 0.f, 0.f), v1 = v0;
        if (row < N) {
            const float4* fp = (const float4*)(feat + (size_t)row * DIM);
            v0 = fp[kq * 2]; v1 = fp[kq * 2 + 1];
        }
        int kb = kq * 8;
        sFT[(kb + 0) * 64 + m] = v0.x; sFT[(kb + 1) * 64 + m] = v0.y;
        sFT[(kb + 2) * 64 + m] = v0.z; sFT[(kb + 3) * 64 + m] = v0.w;
        sFT[(kb + 4) * 64 + m] = v1.x; sFT[(kb + 5) * 64 + m] = v1.y;
        sFT[(kb + 6) * 64 + m] = v1.z; sFT[(kb + 7) * 64 + m] = v1.w;
    }
    __syncthreads();

    int tx = tid & 15;   // col group of 8
    int ty = tid >> 4;   // row group of 8

    unsigned long long acc[8][4];
#pragma unroll
    for (int i = 0; i < 8; i++)
#pragma unroll
        for (int j = 0; j < 4; j++) acc[i][j] = 0ULL;

#pragma unroll 4
    for (int k = 0; k < 128; k++) {
        const float4* ap = (const float4*)&sFT[k * 64 + ty * 8];
        float4 a0 = ap[0], a1 = ap[1];
        const ulonglong2* bp2 = (const ulonglong2*)&sW[k * 128 + tx * 8];
        ulonglong2 bq0 = bp2[0], bq1 = bp2[1];
        unsigned long long bp[4] = {bq0.x, bq0.y, bq1.x, bq1.y};
        unsigned long long ad[8];
        ad[0] = pack2(a0.x, a0.x); ad[1] = pack2(a0.y, a0.y);
        ad[2] = pack2(a0.z, a0.z); ad[3] = pack2(a0.w, a0.w);
        ad[4] = pack2(a1.x, a1.x); ad[5] = pack2(a1.y, a1.y);
        ad[6] = pack2(a1.z, a1.z); ad[7] = pack2(a1.w, a1.w);
#pragma unroll
        for (int i = 0; i < 8; i++)
#pragma unroll
            for (int j = 0; j < 4; j++) fma2(acc[i][j], ad[i], bp[j]);
    }

    float4 bb0 = *(const float4*)&bias[tx * 8];
    float4 bb1 = *(const float4*)&bias[tx * 8 + 4];
#pragma unroll
    for (int i = 0; i < 8; i++) {
        int row = rb + ty * 8 + i;
        if (row >= N) continue;
        float o[8];
        unpack2(acc[i][0], o[0], o[1]);
        unpack2(acc[i][1], o[2], o[3]);
        unpack2(acc[i][2], o[4], o[5]);
        unpack2(acc[i][3], o[6], o[7]);
        o[0]+=bb0.x; o[1]+=bb0.y; o[2]+=bb0.z; o[3]+=bb0.w;
        o[4]+=bb1.x; o[5]+=bb1.y; o[6]+=bb1.z; o[7]+=bb1.w;
        __half2 h0 = __floats2half2_rn(o[0], o[1]);
        __half2 h1 = __floats2half2_rn(o[2], o[3]);
        __half2 h2 = __floats2half2_rn(o[4], o[5]);
        __half2 h3 = __floats2half2_rn(o[6], o[7]);
        uint4 st;
        st.x = *reinterpret_cast<unsigned*>(&h0);
        st.y = *reinterpret_cast<unsigned*>(&h1);
        st.z = *reinterpret_cast<unsigned*>(&h2);
        st.w = *reinterpret_cast<unsigned*>(&h3);
        *reinterpret_cast<uint4*>(&g_hh[(size_t)row * DIM + tx * 8]) = st;
    }
}

// ---------------- K4: fused hist+scatter, 2 independent 4-edge quads/thread -----
// Same inline per-edge pattern as the proven 4-wide version; two quads give
// 8 independent gather->atomic->store chains per thread.
__global__ void scatterhist_kernel(const int* __restrict__ src, const int* __restrict__ dst,
                                   int E, int T) {
    int i = blockIdx.x * blockDim.x + threadIdx.x;
    if (i >= T) return;
    int Q = E >> 2;                 // number of full quads

    // quad A: index i, quad B: index i + T (both guaranteed full quads if < Q)
    int qa = i, qb = i + T;

    if (qa < Q) {
        int4 u4 = __ldg((const int4*)src + qa);
        int4 v4 = __ldg((const int4*)dst + qa);
        int us[4] = {u4.x, u4.y, u4.z, u4.w};
        int vs[4] = {v4.x, v4.y, v4.z, v4.w};
        int4 u4b, v4b;
        int usb[4], vsb[4];
        bool hasB = (qb < Q);
        if (hasB) {
            u4b = __ldg((const int4*)src + qb);
            v4b = __ldg((const int4*)dst + qb);
            usb[0]=u4b.x; usb[1]=u4b.y; usb[2]=u4b.z; usb[3]=u4b.w;
            vsb[0]=v4b.x; vsb[1]=v4b.y; vsb[2]=v4b.z; vsb[3]=v4b.w;
        }
#pragma unroll
        for (int j = 0; j < 4; j++) {
            float sc = __ldg(&g_ssrc[us[j]]);
            int r = atomicAdd(&g_deg[vs[j]], 1);
            if (r < MAXDEG)
                g_csr[((size_t)vs[j] << 7) + r] = make_int2(us[j], __float_as_int(sc));
        }
        if (hasB) {
#pragma unroll
            for (int j = 0; j < 4; j++) {
                float sc = __ldg(&g_ssrc[usb[j]]);
                int r = atomicAdd(&g_deg[vsb[j]], 1);
                if (r < MAXDEG)
                    g_csr[((size_t)vsb[j] << 7) + r] = make_int2(usb[j], __float_as_int(sc));
            }
        }
    }

    // tail edges (E % 4) handled by thread 0
    if (i == 0) {
        for (int j = Q * 4; j < E; j++) {
            int u = src[j], v = dst[j];
            float sc = g_ssrc[u];
            int r = atomicAdd(&g_deg[v], 1);
            if (r < MAXDEG)
                g_csr[((size_t)v << 7) + r] = make_int2(u, __float_as_int(sc));
        }
    }
}

// ---------------- K5: warp-per-dst single-pass softmax-gather -------------------
// No max-shift: scores are O(10) << 88, exp() fp32-safe; ratio identical to
// rounding. Padded CSR: node v owns csr[v*128 .. v*128+deg).
__device__ __forceinline__ void acc8(float* acc, uint4 hv, float w) {
    __half2 h0 = *reinterpret_cast<__half2*>(&hv.x);
    __half2 h1 = *reinterpret_cast<__half2*>(&hv.y);
    __half2 h2 = *reinterpret_cast<__half2*>(&hv.z);
    __half2 h3 = *reinterpret_cast<__half2*>(&hv.w);
    float2 f0 = __half22float2(h0), f1 = __half22float2(h1);
    float2 f2 = __half22float2(h2), f3 = __half22float2(h3);
    acc[0] += w * f0.x; acc[1] += w * f0.y;
    acc[2] += w * f1.x; acc[3] += w * f1.y;
    acc[4] += w * f2.x; acc[5] += w * f2.y;
    acc[6] += w * f3.x; acc[7] += w * f3.y;
}

__global__ void agg_kernel(float* __restrict__ out, const float* __restrict__ attn_b, int N) {
    int gw = (blockIdx.x * blockDim.x + threadIdx.x) >> 5;
    if (gw >= N) return;
    int lane = threadIdx.x & 31;
    int grp = lane >> 4, sub = lane & 15;
    int s = gw << 7;
    int cnt = g_deg[gw];
    cnt = (cnt < MAXDEG) ? cnt : MAXDEG;
    int e = s + cnt;
    float sdv = g_sdst[gw] + attn_b[0];

    float acc[8] = {0.f, 0.f, 0.f, 0.f, 0.f, 0.f, 0.f, 0.f};
    float den = 0.f;
    int jb = s;
    for (; jb + 16 <= e; jb += 16) {
#pragma unroll
        for (int tt = 0; tt < 8; tt++) {
            int2 p = __ldg(&g_csr[jb + 2 * tt + grp]);
            float r = __int_as_float(p.y) + sdv;
            r = (r >= 0.f) ? r : NEG_SLOPE * r;
            float w = __expf(r);
            den += w;
            uint4 hv = __ldg(reinterpret_cast<const uint4*>(&g_hh[(size_t)p.x * DIM + sub * 8]));
            acc8(acc, hv, w);
        }
    }
    for (; jb < e; jb += 2) {
        int j = jb + grp;
        int2 p = (j < e) ? __ldg(&g_csr[j]) : make_int2(0, (int)0xFF800000);  // -inf -> w=0
        float r = __int_as_float(p.y) + sdv;
        r = (r >= 0.f) ? r : NEG_SLOPE * r;
        float w = __expf(r);
        den += w;
        uint4 hv = __ldg(reinterpret_cast<const uint4*>(&g_hh[(size_t)p.x * DIM + sub * 8]));
        acc8(acc, hv, w);
    }

#pragma unroll
    for (int k = 0; k < 8; k++) acc[k] += __shfl_xor_sync(0xffffffffu, acc[k], 16);
#pragma unroll
    for (int o = 16; o > 0; o >>= 1) den += __shfl_xor_sync(0xffffffffu, den, o);
    den *= 0.0625f;   // each edge's w counted by its 16-lane group

    float inv = (den > 0.f) ? (1.f / den) : 0.f;
    if (grp == 0) {
        float4 o0 = make_float4(acc[0] * inv, acc[1] * inv, acc[2] * inv, acc[3] * inv);
        float4 o1 = make_float4(acc[4] * inv, acc[5] * inv, acc[6] * inv, acc[7] * inv);
        float4* op = (float4*)(out + (size_t)gw * DIM + sub * 8);
        op[0] = o0;
        op[1] = o1;
    }
}

// ---------------- launch --------------------------------------------------------
extern "C" void kernel_launch(void* const* d_in, const int* in_sizes, int n_in,
                              void* d_out, int out_size) {
    const float* feat   = (const float*)d_in[0];
    const int*   src    = (const int*)d_in[1];
    const int*   dst    = (const int*)d_in[2];
    const float* W      = (const float*)d_in[3];
    const float* bias   = (const float*)d_in[4];
    const float* attn_w = (const float*)d_in[5];
    const float* attn_b = (const float*)d_in[6];
    const float* mask   = (const float*)d_in[7];
    float* out = (float*)d_out;

    int N = in_sizes[0] / DIM;   // 50000
    int E = in_sizes[1];         // 1600000

    static cudaStream_t s_side = nullptr;
    static cudaEvent_t ev_prep = nullptr, ev_scat = nullptr;
    if (s_side == nullptr) {
        cudaStreamCreateWithFlags(&s_side, cudaStreamNonBlocking);
        cudaEventCreateWithFlags(&ev_prep, cudaEventDisableTiming);
        cudaEventCreateWithFlags(&ev_scat, cudaEventDisableTiming);
    }

    int Q = E >> 2;              // full quads
    int T = (Q + 1) / 2;         // threads; each does quads i and i+T

    // main: prep (Wp fold + zero deg)
    prep_kernel<<<(N_NODES + 255) / 256, 256>>>(W, mask);
    cudaEventRecord(ev_prep, 0);

    // side: fold -> score -> scatterhist (overlaps GEMM)
    cudaStreamWaitEvent(s_side, ev_prep, 0);
    fold_kernel<<<16, 256, 0, s_side>>>(attn_w, bias);
    score_kernel<<<(N * 32 + 255) / 256, 256, 0, s_side>>>(feat, N);
    scatterhist_kernel<<<(T + 255) / 256, 256, 0, s_side>>>(src, dst, E, T);
    cudaEventRecord(ev_scat, s_side);

    // main: GEMM (h fp16)
    size_t smem = (size_t)(128 * 64 + 128 * 128) * sizeof(float);  // 96KB
    cudaFuncSetAttribute(gemm_kernel, cudaFuncAttributeMaxDynamicSharedMemorySize, (int)smem);
    gemm_kernel<<<(N + GB_M - 1) / GB_M, 128, smem>>>(feat, bias, N);

    // join, then aggregate
    cudaStreamWaitEvent(0, ev_scat, 0);
    agg_kernel<<<(N * 32 + 255) / 256, 256>>>(out, attn_b, N);
}

// round 16
// speedup vs baseline: 1.0127x; 1.0127x over previous
#include <cuda_runtime.h>
#include <cuda_fp16.h>
#include <math.h>

#define N_NODES 50000
#define N_EDGES 1600000
#define DIM 128
#define NEG_SLOPE 0.01f
#define MAXDEG 128            // Poisson(32) -> P(deg>=128) ~ 0 (11+ sigma); guarded anyway

// ---------------- scratch (static device globals; no allocation) ----------------
__device__ float  g_Wp[DIM * DIM];                     // sigmoid(mask) folded into W
__device__ float  g_w1f[DIM];                          // Wp @ aw1 (score fold, src)
__device__ float  g_w2f[DIM];                          // Wp @ aw2 (score fold, dst)
__device__ float  g_sb[2];                             // b@aw1, b@aw2
__device__ __half g_hh[(size_t)N_NODES * DIM];         // projected features (fp16)
__device__ float  g_ssrc[N_NODES];
__device__ float  g_sdst[N_NODES];
__device__ int    g_deg[N_NODES];
__device__ int2   g_csr[(size_t)N_NODES * MAXDEG];     // padded CSR {src, s_src-bits}

// ---------------- f32x2 packed FMA helpers (sm_103a) ----------------------------
__device__ __forceinline__ unsigned long long pack2(float lo, float hi) {
    unsigned long long r;
    asm("mov.b64 %0,{%1,%2};" : "=l"(r) : "f"(lo), "f"(hi));
    return r;
}
__device__ __forceinline__ void unpack2(unsigned long long v, float& lo, float& hi) {
    asm("mov.b64 {%0,%1},%2;" : "=f"(lo), "=f"(hi) : "l"(v));
}
__device__ __forceinline__ void fma2(unsigned long long& d, unsigned long long a, unsigned long long b) {
    asm("fma.rn.f32x2 %0,%1,%2,%0;" : "+l"(d) : "l"(a), "l"(b));
}

// ---------------- K0 (main): fold sigmoid(mask) into W --------------------------
__global__ void prep_w_kernel(const float* __restrict__ W, const float* __restrict__ mask) {
    int i = blockIdx.x * blockDim.x + threadIdx.x;
    if (i < DIM * DIM) {
        int k = i >> 7;
        float s = 1.f / (1.f + __expf(-mask[k]));
        g_Wp[i] = W[i] * s;
    }
}

// ---------------- K1 (side): fold attn_w through W·sig(mask) + zero deg ---------
// Independent of prep: computes Wp rows on the fly from W and mask.
// Blocks 0..15 do the fold math; ALL blocks zero a slice of g_deg.
__global__ __launch_bounds__(256) void fold_kernel(const float* __restrict__ W,
                                                   const float* __restrict__ mask,
                                                   const float* __restrict__ attn_w,
                                                   const float* __restrict__ bias) {
    // zero deg histogram (whole grid)
    int gi = blockIdx.x * blockDim.x + threadIdx.x;
    if (gi < N_NODES) g_deg[gi] = 0;

    if (blockIdx.x >= 16) return;

    int gw = blockIdx.x * 8 + (threadIdx.x >> 5);   // 0..127 = row index
    int lane = threadIdx.x & 31;
    float4 v1 = ((const float4*)attn_w)[lane];          // aw1 chunk
    float4 v2 = ((const float4*)attn_w)[32 + lane];     // aw2 chunk
    float sgm = 1.f / (1.f + __expf(-mask[gw]));
    float4 wv = ((const float4*)&W[gw * DIM])[lane];
    wv.x *= sgm; wv.y *= sgm; wv.z *= sgm; wv.w *= sgm;
    float p1 = wv.x * v1.x + wv.y * v1.y + wv.z * v1.z + wv.w * v1.w;
    float p2 = wv.x * v2.x + wv.y * v2.y + wv.z * v2.z + wv.w * v2.w;
#pragma unroll
    for (int o = 16; o > 0; o >>= 1) {
        p1 += __shfl_xor_sync(0xffffffffu, p1, o);
        p2 += __shfl_xor_sync(0xffffffffu, p2, o);
    }
    if (lane == 0) { g_w1f[gw] = p1; g_w2f[gw] = p2; }
    // bias dots (block 0, warp 0)
    if (blockIdx.x == 0 && (threadIdx.x >> 5) == 0) {
        float4 bv = ((const float4*)bias)[lane];
        float q1 = bv.x * v1.x + bv.y * v1.y + bv.z * v1.z + bv.w * v1.w;
        float q2 = bv.x * v2.x + bv.y * v2.y + bv.z * v2.z + bv.w * v2.w;
#pragma unroll
        for (int o = 16; o > 0; o >>= 1) {
            q1 += __shfl_xor_sync(0xffffffffu, q1, o);
            q2 += __shfl_xor_sync(0xffffffffu, q2, o);
        }
        if (lane == 0) { g_sb[0] = q1; g_sb[1] = q2; }
    }
}

// ---------------- K2 (side): node scores straight from feat (warp per node) -----
__global__ void score_kernel(const float* __restrict__ feat, int N) {
    int gw = (blockIdx.x * blockDim.x + threadIdx.x) >> 5;
    int lane = threadIdx.x & 31;
    if (gw >= N) return;
    float4 f4 = ((const float4*)(feat + (size_t)gw * DIM))[lane];
    float4 w1 = ((const float4*)g_w1f)[lane];
    float4 w2 = ((const float4*)g_w2f)[lane];
    float s1 = f4.x * w1.x + f4.y * w1.y + f4.z * w1.z + f4.w * w1.w;
    float s2 = f4.x * w2.x + f4.y * w2.y + f4.z * w2.z + f4.w * w2.w;
#pragma unroll
    for (int o = 16; o > 0; o >>= 1) {
        s1 += __shfl_xor_sync(0xffffffffu, s1, o);
        s2 += __shfl_xor_sync(0xffffffffu, s2, o);
    }
    if (lane == 0) {
        g_ssrc[gw] = s1 + g_sb[0];
        g_sdst[gw] = s2 + g_sb[1];
    }
}

// ---------------- K3 (main): h = feat @ Wp + b (fp16 out) -----------------------
#define GB_M 64
__global__ __launch_bounds__(128) void gemm_kernel(const float* __restrict__ feat,
                                                   const float* __restrict__ bias, int N) {
    extern __shared__ float sm[];
    float* sFT = sm;              // [128 k][64 m] transposed feat tile (32KB)
    float* sW  = sm + 128 * 64;   // [128 k][128 n] (64KB)
    int tid = threadIdx.x;
    int rb = blockIdx.x * GB_M;

    const float4* Wp4 = (const float4*)g_Wp;
    float4* sW4 = (float4*)sW;
#pragma unroll
    for (int i = 0; i < 32; i++) sW4[tid + i * 128] = Wp4[tid + i * 128];

#pragma unroll
    for (int it = 0; it < 8; it++) {
        int idx = tid + it * 128;
        int m = idx & 63, kq = idx >> 6;
        int row = rb + m;
        float4 v0 = make_float4(0.f, 0.f, 0.f, 0.f), v1 = v0;
        if (row < N) {
            const float4* fp = (const float4*)(feat + (size_t)row * DIM);
            v0 = fp[kq * 2]; v1 = fp[kq * 2 + 1];
        }
        int kb = kq * 8;
        sFT[(kb + 0) * 64 + m] = v0.x; sFT[(kb + 1) * 64 + m] = v0.y;
        sFT[(kb + 2) * 64 + m] = v0.z; sFT[(kb + 3) * 64 + m] = v0.w;
        sFT[(kb + 4) * 64 + m] = v1.x; sFT[(kb + 5) * 64 + m] = v1.y;
        sFT[(kb + 6) * 64 + m] = v1.z; sFT[(kb + 7) * 64 + m] = v1.w;
    }
    __syncthreads();

    int tx = tid & 15;   // col group of 8
    int ty = tid >> 4;   // row group of 8

    unsigned long long acc[8][4];
#pragma unroll
    for (int i = 0; i < 8; i++)
#pragma unroll
        for (int j = 0; j < 4; j++) acc[i][j] = 0ULL;

#pragma unroll 4
    for (int k = 0; k < 128; k++) {
        const float4* ap = (const float4*)&sFT[k * 64 + ty * 8];
        float4 a0 = ap[0], a1 = ap[1];
        const ulonglong2* bp2 = (const ulonglong2*)&sW[k * 128 + tx * 8];
        ulonglong2 bq0 = bp2[0], bq1 = bp2[1];
        unsigned long long bp[4] = {bq0.x, bq0.y, bq1.x, bq1.y};
        unsigned long long ad[8];
        ad[0] = pack2(a0.x, a0.x); ad[1] = pack2(a0.y, a0.y);
        ad[2] = pack2(a0.z, a0.z); ad[3] = pack2(a0.w, a0.w);
        ad[4] = pack2(a1.x, a1.x); ad[5] = pack2(a1.y, a1.y);
        ad[6] = pack2(a1.z, a1.z); ad[7] = pack2(a1.w, a1.w);
#pragma unroll
        for (int i = 0; i < 8; i++)
#pragma unroll
            for (int j = 0; j < 4; j++) fma2(acc[i][j], ad[i], bp[j]);
    }

    float4 bb0 = *(const float4*)&bias[tx * 8];
    float4 bb1 = *(const float4*)&bias[tx * 8 + 4];
#pragma unroll
    for (int i = 0; i < 8; i++) {
        int row = rb + ty * 8 + i;
        if (row >= N) continue;
        float o[8];
        unpack2(acc[i][0], o[0], o[1]);
        unpack2(acc[i][1], o[2], o[3]);
        unpack2(acc[i][2], o[4], o[5]);
        unpack2(acc[i][3], o[6], o[7]);
        o[0]+=bb0.x; o[1]+=bb0.y; o[2]+=bb0.z; o[3]+=bb0.w;
        o[4]+=bb1.x; o[5]+=bb1.y; o[6]+=bb1.z; o[7]+=bb1.w;
        __half2 h0 = __floats2half2_rn(o[0], o[1]);
        __half2 h1 = __floats2half2_rn(o[2], o[3]);
        __half2 h2 = __floats2half2_rn(o[4], o[5]);
        __half2 h3 = __floats2half2_rn(o[6], o[7]);
        uint4 st;
        st.x = *reinterpret_cast<unsigned*>(&h0);
        st.y = *reinterpret_cast<unsigned*>(&h1);
        st.z = *reinterpret_cast<unsigned*>(&h2);
        st.w = *reinterpret_cast<unsigned*>(&h3);
        *reinterpret_cast<uint4*>(&g_hh[(size_t)row * DIM + tx * 8]) = st;
    }
}

// ---------------- K4 (side): fused hist+scatter into padded CSR (4/thread) ------
__global__ void scatterhist_kernel(const int* __restrict__ src, const int* __restrict__ dst, int E) {
    int i = blockIdx.x * blockDim.x + threadIdx.x;
    int i4 = i * 4;
    if (i4 >= E) return;
    if (i4 + 3 < E) {
        int4 u4 = __ldg((const int4*)src + i);
        int4 v4 = __ldg((const int4*)dst + i);
        int us[4] = {u4.x, u4.y, u4.z, u4.w};
        int vs[4] = {v4.x, v4.y, v4.z, v4.w};
#pragma unroll
        for (int j = 0; j < 4; j++) {
            float sc = __ldg(&g_ssrc[us[j]]);
            int r = atomicAdd(&g_deg[vs[j]], 1);
            if (r < MAXDEG)
                g_csr[((size_t)vs[j] << 7) + r] = make_int2(us[j], __float_as_int(sc));
        }
    } else {
        for (int j = i4; j < E; j++) {
            int u = src[j], v = dst[j];
            float sc = g_ssrc[u];
            int r = atomicAdd(&g_deg[v], 1);
            if (r < MAXDEG)
                g_csr[((size_t)v << 7) + r] = make_int2(u, __float_as_int(sc));
        }
    }
}

// ---------------- K5: warp-per-dst single-pass softmax-gather -------------------
// No max-shift: scores are O(10) << 88, exp() fp32-safe; ratio identical to
// rounding. Padded CSR: node v owns csr[v*128 .. v*128+deg).
__device__ __forceinline__ void acc8(float* acc, uint4 hv, float w) {
    __half2 h0 = *reinterpret_cast<__half2*>(&hv.x);
    __half2 h1 = *reinterpret_cast<__half2*>(&hv.y);
    __half2 h2 = *reinterpret_cast<__half2*>(&hv.z);
    __half2 h3 = *reinterpret_cast<__half2*>(&hv.w);
    float2 f0 = __half22float2(h0), f1 = __half22float2(h1);
    float2 f2 = __half22float2(h2), f3 = __half22float2(h3);
    acc[0] += w * f0.x; acc[1] += w * f0.y;
    acc[2] += w * f1.x; acc[3] += w * f1.y;
    acc[4] += w * f2.x; acc[5] += w * f2.y;
    acc[6] += w * f3.x; acc[7] += w * f3.y;
}

__global__ void agg_kernel(float* __restrict__ out, const float* __restrict__ attn_b, int N) {
    int gw = (blockIdx.x * blockDim.x + threadIdx.x) >> 5;
    if (gw >= N) return;
    int lane = threadIdx.x & 31;
    int grp = lane >> 4, sub = lane & 15;
    int s = gw << 7;
    int cnt = g_deg[gw];
    cnt = (cnt < MAXDEG) ? cnt : MAXDEG;
    int e = s + cnt;
    float sdv = g_sdst[gw] + attn_b[0];

    float acc[8] = {0.f, 0.f, 0.f, 0.f, 0.f, 0.f, 0.f, 0.f};
    float den = 0.f;
    int jb = s;
    for (; jb + 16 <= e; jb += 16) {
#pragma unroll
        for (int tt = 0; tt < 8; tt++) {
            int2 p = __ldg(&g_csr[jb + 2 * tt + grp]);
            float r = __int_as_float(p.y) + sdv;
            r = (r >= 0.f) ? r : NEG_SLOPE * r;
            float w = __expf(r);
            den += w;
            uint4 hv = __ldg(reinterpret_cast<const uint4*>(&g_hh[(size_t)p.x * DIM + sub * 8]));
            acc8(acc, hv, w);
        }
    }
    for (; jb < e; jb += 2) {
        int j = jb + grp;
        int2 p = (j < e) ? __ldg(&g_csr[j]) : make_int2(0, (int)0xFF800000);  // -inf -> w=0
        float r = __int_as_float(p.y) + sdv;
        r = (r >= 0.f) ? r : NEG_SLOPE * r;
        float w = __expf(r);
        den += w;
        uint4 hv = __ldg(reinterpret_cast<const uint4*>(&g_hh[(size_t)p.x * DIM + sub * 8]));
        acc8(acc, hv, w);
    }

#pragma unroll
    for (int k = 0; k < 8; k++) acc[k] += __shfl_xor_sync(0xffffffffu, acc[k], 16);
#pragma unroll
    for (int o = 16; o > 0; o >>= 1) den += __shfl_xor_sync(0xffffffffu, den, o);
    den *= 0.0625f;   // each edge's w counted by its 16-lane group

    float inv = (den > 0.f) ? (1.f / den) : 0.f;
    if (grp == 0) {
        float4 o0 = make_float4(acc[0] * inv, acc[1] * inv, acc[2] * inv, acc[3] * inv);
        float4 o1 = make_float4(acc[4] * inv, acc[5] * inv, acc[6] * inv, acc[7] * inv);
        float4* op = (float4*)(out + (size_t)gw * DIM + sub * 8);
        op[0] = o0;
        op[1] = o1;
    }
}

// ---------------- launch --------------------------------------------------------
extern "C" void kernel_launch(void* const* d_in, const int* in_sizes, int n_in,
                              void* d_out, int out_size) {
    const float* feat   = (const float*)d_in[0];
    const int*   src    = (const int*)d_in[1];
    const int*   dst    = (const int*)d_in[2];
    const float* W      = (const float*)d_in[3];
    const float* bias   = (const float*)d_in[4];
    const float* attn_w = (const float*)d_in[5];
    const float* attn_b = (const float*)d_in[6];
    const float* mask   = (const float*)d_in[7];
    float* out = (float*)d_out;

    int N = in_sizes[0] / DIM;   // 50000
    int E = in_sizes[1];         // 1600000

    static cudaStream_t s_side = nullptr;
    static cudaEvent_t ev_root = nullptr, ev_scat = nullptr;
    if (s_side == nullptr) {
        cudaStreamCreateWithFlags(&s_side, cudaStreamNonBlocking);
        cudaEventCreateWithFlags(&ev_root, cudaEventDisableTiming);
        cudaEventCreateWithFlags(&ev_scat, cudaEventDisableTiming);
    }

    int e4 = (E + 3) / 4;
    int foldBlocks = (N_NODES + 255) / 256;   // 196 blocks: blocks 0-15 fold, all zero deg

    // fork root so the side stream starts at t=0 within the graph
    cudaEventRecord(ev_root, 0);
    cudaStreamWaitEvent(s_side, ev_root, 0);

    // side: fold(+degzero, no deps) -> score -> scatterhist
    fold_kernel<<<foldBlocks, 256, 0, s_side>>>(W, mask, attn_w, bias);
    score_kernel<<<(N * 32 + 255) / 256, 256, 0, s_side>>>(feat, N);
    scatterhist_kernel<<<(e4 + 255) / 256, 256, 0, s_side>>>(src, dst, E);
    cudaEventRecord(ev_scat, s_side);

    // main: prep Wp -> GEMM (h fp16)
    prep_w_kernel<<<(DIM * DIM + 255) / 256, 256>>>(W, mask);
    size_t smem = (size_t)(128 * 64 + 128 * 128) * sizeof(float);  // 96KB
    cudaFuncSetAttribute(gemm_kernel, cudaFuncAttributeMaxDynamicSharedMemorySize, (int)smem);
    gemm_kernel<<<(N + GB_M - 1) / GB_M, 128, smem>>>(feat, bias, N);

    // join, then aggregate
    cudaStreamWaitEvent(0, ev_scat, 0);
    agg_kernel<<<(N * 32 + 255) / 256, 256>>>(out, attn_b, N);
}

// round 17
// speedup vs baseline: 1.0135x; 1.0008x over previous
#include <cuda_runtime.h>
#include <cuda_fp16.h>
#include <math.h>

#define N_NODES 50000
#define N_EDGES 1600000
#define DIM 128
#define NEG_SLOPE 0.01f
#define MAXDEG 128            // Poisson(32) -> P(deg>=128) ~ 0 (11+ sigma); guarded anyway

// ---------------- scratch (static device globals; no allocation) ----------------
__device__ float  g_w1f[DIM];                          // (W·sig) @ aw1 (score fold, src)
__device__ float  g_w2f[DIM];                          // (W·sig) @ aw2 (score fold, dst)
__device__ float  g_sb[2];                             // b@aw1, b@aw2
__device__ __half g_hh[(size_t)N_NODES * DIM];         // projected features (fp16)
__device__ float  g_ssrc[N_NODES];
__device__ float  g_sdst[N_NODES];
__device__ int    g_deg[N_NODES];
__device__ int2   g_csr[(size_t)N_NODES * MAXDEG];     // padded CSR {src, s_src-bits}

// ---------------- f32x2 packed FMA helpers (sm_103a) ----------------------------
__device__ __forceinline__ unsigned long long pack2(float lo, float hi) {
    unsigned long long r;
    asm("mov.b64 %0,{%1,%2};" : "=l"(r) : "f"(lo), "f"(hi));
    return r;
}
__device__ __forceinline__ void unpack2(unsigned long long v, float& lo, float& hi) {
    asm("mov.b64 {%0,%1},%2;" : "=f"(lo), "=f"(hi) : "l"(v));
}
__device__ __forceinline__ void fma2(unsigned long long& d, unsigned long long a, unsigned long long b) {
    asm("fma.rn.f32x2 %0,%1,%2,%0;" : "+l"(d) : "l"(a), "l"(b));
}

// ---------------- K1 (side): fold attn_w through W·sig(mask) + zero deg ---------
// Blocks 0..15 do the fold math; ALL blocks zero a slice of g_deg.
__global__ __launch_bounds__(256) void fold_kernel(const float* __restrict__ W,
                                                   const float* __restrict__ mask,
                                                   const float* __restrict__ attn_w,
                                                   const float* __restrict__ bias) {
    int gi = blockIdx.x * blockDim.x + threadIdx.x;
    if (gi < N_NODES) g_deg[gi] = 0;

    if (blockIdx.x >= 16) return;

    int gw = blockIdx.x * 8 + (threadIdx.x >> 5);   // 0..127 = row index
    int lane = threadIdx.x & 31;
    float4 v1 = ((const float4*)attn_w)[lane];          // aw1 chunk
    float4 v2 = ((const float4*)attn_w)[32 + lane];     // aw2 chunk
    float sgm = 1.f / (1.f + __expf(-mask[gw]));
    float4 wv = ((const float4*)&W[gw * DIM])[lane];
    wv.x *= sgm; wv.y *= sgm; wv.z *= sgm; wv.w *= sgm;
    float p1 = wv.x * v1.x + wv.y * v1.y + wv.z * v1.z + wv.w * v1.w;
    float p2 = wv.x * v2.x + wv.y * v2.y + wv.z * v2.z + wv.w * v2.w;
#pragma unroll
    for (int o = 16; o > 0; o >>= 1) {
        p1 += __shfl_xor_sync(0xffffffffu, p1, o);
        p2 += __shfl_xor_sync(0xffffffffu, p2, o);
    }
    if (lane == 0) { g_w1f[gw] = p1; g_w2f[gw] = p2; }
    // bias dots (block 0, warp 0)
    if (blockIdx.x == 0 && (threadIdx.x >> 5) == 0) {
        float4 bv = ((const float4*)bias)[lane];
        float q1 = bv.x * v1.x + bv.y * v1.y + bv.z * v1.z + bv.w * v1.w;
        float q2 = bv.x * v2.x + bv.y * v2.y + bv.z * v2.z + bv.w * v2.w;
#pragma unroll
        for (int o = 16; o > 0; o >>= 1) {
            q1 += __shfl_xor_sync(0xffffffffu, q1, o);
            q2 += __shfl_xor_sync(0xffffffffu, q2, o);
        }
        if (lane == 0) { g_sb[0] = q1; g_sb[1] = q2; }
    }
}

// ---------------- K2 (side): node scores straight from feat (warp per node) -----
__global__ void score_kernel(const float* __restrict__ feat, int N) {
    int gw = (blockIdx.x * blockDim.x + threadIdx.x) >> 5;
    int lane = threadIdx.x & 31;
    if (gw >= N) return;
    float4 f4 = ((const float4*)(feat + (size_t)gw * DIM))[lane];
    float4 w1 = ((const float4*)g_w1f)[lane];
    float4 w2 = ((const float4*)g_w2f)[lane];
    float s1 = f4.x * w1.x + f4.y * w1.y + f4.z * w1.z + f4.w * w1.w;
    float s2 = f4.x * w2.x + f4.y * w2.y + f4.z * w2.z + f4.w * w2.w;
#pragma unroll
    for (int o = 16; o > 0; o >>= 1) {
        s1 += __shfl_xor_sync(0xffffffffu, s1, o);
        s2 += __shfl_xor_sync(0xffffffffu, s2, o);
    }
    if (lane == 0) {
        g_ssrc[gw] = s1 + g_sb[0];
        g_sdst[gw] = s2 + g_sb[1];
    }
}

// ---------------- K3 (main): h = feat @ (W·sig(mask)) + b (fp16 out) ------------
// Mask-sigmoid folded in during the W smem stage (no separate prep kernel).
#define GB_M 64
__global__ __launch_bounds__(128) void gemm_kernel(const float* __restrict__ feat,
                                                   const float* __restrict__ W,
                                                   const float* __restrict__ mask,
                                                   const float* __restrict__ bias, int N) {
    extern __shared__ float sm[];
    __shared__ float sSig[DIM];
    float* sFT = sm;              // [128 k][64 m] transposed feat tile (32KB)
    float* sW  = sm + 128 * 64;   // [128 k][128 n] (64KB)
    int tid = threadIdx.x;
    int rb = blockIdx.x * GB_M;

    // per-row sigmoid of mask (one exp per row, cached in smem)
    if (tid < DIM) sSig[tid] = 1.f / (1.f + __expf(-mask[tid]));
    __syncthreads();

    // stage W with sigmoid fold: 4096 float4, coalesced
    const float4* W4 = (const float4*)W;
    float4* sW4 = (float4*)sW;
#pragma unroll
    for (int i = 0; i < 32; i++) {
        int fidx = tid + i * 128;
        float s = sSig[fidx >> 5];          // 32 float4 per k-row
        float4 v = __ldg(W4 + fidx);
        v.x *= s; v.y *= s; v.z *= s; v.w *= s;
        sW4[fidx] = v;
    }

#pragma unroll
    for (int it = 0; it < 8; it++) {
        int idx = tid + it * 128;
        int m = idx & 63, kq = idx >> 6;
        int row = rb + m;
        float4 v0 = make_float4(0.f, 0.f, 0.f, 0.f), v1 = v0;
        if (row < N) {
            const float4* fp = (const float4*)(feat + (size_t)row * DIM);
            v0 = fp[kq * 2]; v1 = fp[kq * 2 + 1];
        }
        int kb = kq * 8;
        sFT[(kb + 0) * 64 + m] = v0.x; sFT[(kb + 1) * 64 + m] = v0.y;
        sFT[(kb + 2) * 64 + m] = v0.z; sFT[(kb + 3) * 64 + m] = v0.w;
        sFT[(kb + 4) * 64 + m] = v1.x; sFT[(kb + 5) * 64 + m] = v1.y;
        sFT[(kb + 6) * 64 + m] = v1.z; sFT[(kb + 7) * 64 + m] = v1.w;
    }
    __syncthreads();

    int tx = tid & 15;   // col group of 8
    int ty = tid >> 4;   // row group of 8

    unsigned long long acc[8][4];
#pragma unroll
    for (int i = 0; i < 8; i++)
#pragma unroll
        for (int j = 0; j < 4; j++) acc[i][j] = 0ULL;

#pragma unroll 4
    for (int k = 0; k < 128; k++) {
        const float4* ap = (const float4*)&sFT[k * 64 + ty * 8];
        float4 a0 = ap[0], a1 = ap[1];
        const ulonglong2* bp2 = (const ulonglong2*)&sW[k * 128 + tx * 8];
        ulonglong2 bq0 = bp2[0], bq1 = bp2[1];
        unsigned long long bp[4] = {bq0.x, bq0.y, bq1.x, bq1.y};
        unsigned long long ad[8];
        ad[0] = pack2(a0.x, a0.x); ad[1] = pack2(a0.y, a0.y);
        ad[2] = pack2(a0.z, a0.z); ad[3] = pack2(a0.w, a0.w);
        ad[4] = pack2(a1.x, a1.x); ad[5] = pack2(a1.y, a1.y);
        ad[6] = pack2(a1.z, a1.z); ad[7] = pack2(a1.w, a1.w);
#pragma unroll
        for (int i = 0; i < 8; i++)
#pragma unroll
            for (int j = 0; j < 4; j++) fma2(acc[i][j], ad[i], bp[j]);
    }

    float4 bb0 = *(const float4*)&bias[tx * 8];
    float4 bb1 = *(const float4*)&bias[tx * 8 + 4];
#pragma unroll
    for (int i = 0; i < 8; i++) {
        int row = rb + ty * 8 + i;
        if (row >= N) continue;
        float o[8];
        unpack2(acc[i][0], o[0], o[1]);
        unpack2(acc[i][1], o[2], o[3]);
        unpack2(acc[i][2], o[4], o[5]);
        unpack2(acc[i][3], o[6], o[7]);
        o[0]+=bb0.x; o[1]+=bb0.y; o[2]+=bb0.z; o[3]+=bb0.w;
        o[4]+=bb1.x; o[5]+=bb1.y; o[6]+=bb1.z; o[7]+=bb1.w;
        __half2 h0 = __floats2half2_rn(o[0], o[1]);
        __half2 h1 = __floats2half2_rn(o[2], o[3]);
        __half2 h2 = __floats2half2_rn(o[4], o[5]);
        __half2 h3 = __floats2half2_rn(o[6], o[7]);
        uint4 st;
        st.x = *reinterpret_cast<unsigned*>(&h0);
        st.y = *reinterpret_cast<unsigned*>(&h1);
        st.z = *reinterpret_cast<unsigned*>(&h2);
        st.w = *reinterpret_cast<unsigned*>(&h3);
        *reinterpret_cast<uint4*>(&g_hh[(size_t)row * DIM + tx * 8]) = st;
    }
}

// ---------------- K4 (side): fused hist+scatter into padded CSR (4/thread) ------
__global__ void scatterhist_kernel(const int* __restrict__ src, const int* __restrict__ dst, int E) {
    int i = blockIdx.x * blockDim.x + threadIdx.x;
    int i4 = i * 4;
    if (i4 >= E) return;
    if (i4 + 3 < E) {
        int4 u4 = __ldg((const int4*)src + i);
        int4 v4 = __ldg((const int4*)dst + i);
        int us[4] = {u4.x, u4.y, u4.z, u4.w};
        int vs[4] = {v4.x, v4.y, v4.z, v4.w};
#pragma unroll
        for (int j = 0; j < 4; j++) {
            float sc = __ldg(&g_ssrc[us[j]]);
            int r = atomicAdd(&g_deg[vs[j]], 1);
            if (r < MAXDEG)
                g_csr[((size_t)vs[j] << 7) + r] = make_int2(us[j], __float_as_int(sc));
        }
    } else {
        for (int j = i4; j < E; j++) {
            int u = src[j], v = dst[j];
            float sc = g_ssrc[u];
            int r = atomicAdd(&g_deg[v], 1);
            if (r < MAXDEG)
                g_csr[((size_t)v << 7) + r] = make_int2(u, __float_as_int(sc));
        }
    }
}

// ---------------- K5: warp-per-dst single-pass softmax-gather -------------------
// No max-shift: scores are O(10) << 88, exp() fp32-safe; ratio identical to
// rounding. Padded CSR: node v owns csr[v*128 .. v*128+deg).
__device__ __forceinline__ void acc8(float* acc, uint4 hv, float w) {
    __half2 h0 = *reinterpret_cast<__half2*>(&hv.x);
    __half2 h1 = *reinterpret_cast<__half2*>(&hv.y);
    __half2 h2 = *reinterpret_cast<__half2*>(&hv.z);
    __half2 h3 = *reinterpret_cast<__half2*>(&hv.w);
    float2 f0 = __half22float2(h0), f1 = __half22float2(h1);
    float2 f2 = __half22float2(h2), f3 = __half22float2(h3);
    acc[0] += w * f0.x; acc[1] += w * f0.y;
    acc[2] += w * f1.x; acc[3] += w * f1.y;
    acc[4] += w * f2.x; acc[5] += w * f2.y;
    acc[6] += w * f3.x; acc[7] += w * f3.y;
}

__global__ void agg_kernel(float* __restrict__ out, const float* __restrict__ attn_b, int N) {
    int gw = (blockIdx.x * blockDim.x + threadIdx.x) >> 5;
    if (gw >= N) return;
    int lane = threadIdx.x & 31;
    int grp = lane >> 4, sub = lane & 15;
    int s = gw << 7;
    int cnt = g_deg[gw];
    cnt = (cnt < MAXDEG) ? cnt : MAXDEG;
    int e = s + cnt;
    float sdv = g_sdst[gw] + attn_b[0];

    float acc[8] = {0.f, 0.f, 0.f, 0.f, 0.f, 0.f, 0.f, 0.f};
    float den = 0.f;
    int jb = s;
    for (; jb + 16 <= e; jb += 16) {
#pragma unroll
        for (int tt = 0; tt < 8; tt++) {
            int2 p = __ldg(&g_csr[jb + 2 * tt + grp]);
            float r = __int_as_float(p.y) + sdv;
            r = (r >= 0.f) ? r : NEG_SLOPE * r;
            float w = __expf(r);
            den += w;
            uint4 hv = __ldg(reinterpret_cast<const uint4*>(&g_hh[(size_t)p.x * DIM + sub * 8]));
            acc8(acc, hv, w);
        }
    }
    // tail: one 16-wide step with CLAMPED indices (loads always valid &
    // initialized; predicate only zeroes w). Safe-unroll form.
    if (jb < e) {
        int last = e - 1;
#pragma unroll
        for (int tt = 0; tt < 8; tt++) {
            int jc = jb + 2 * tt + grp;
            int j = (jc < e) ? jc : last;
            int2 p = __ldg(&g_csr[j]);
            float r = __int_as_float(p.y) + sdv;
            r = (r >= 0.f) ? r : NEG_SLOPE * r;
            float w = (jc < e) ? __expf(r) : 0.f;
            den += w;
            uint4 hv = __ldg(reinterpret_cast<const uint4*>(&g_hh[(size_t)p.x * DIM + sub * 8]));
            acc8(acc, hv, w);
        }
    }

#pragma unroll
    for (int k = 0; k < 8; k++) acc[k] += __shfl_xor_sync(0xffffffffu, acc[k], 16);
#pragma unroll
    for (int o = 16; o > 0; o >>= 1) den += __shfl_xor_sync(0xffffffffu, den, o);
    den *= 0.0625f;   // each edge's w counted by its 16-lane group

    float inv = (den > 0.f) ? (1.f / den) : 0.f;
    if (grp == 0) {
        float4 o0 = make_float4(acc[0] * inv, acc[1] * inv, acc[2] * inv, acc[3] * inv);
        float4 o1 = make_float4(acc[4] * inv, acc[5] * inv, acc[6] * inv, acc[7] * inv);
        float4* op = (float4*)(out + (size_t)gw * DIM + sub * 8);
        op[0] = o0;
        op[1] = o1;
    }
}

// ---------------- launch --------------------------------------------------------
extern "C" void kernel_launch(void* const* d_in, const int* in_sizes, int n_in,
                              void* d_out, int out_size) {
    const float* feat   = (const float*)d_in[0];
    const int*   src    = (const int*)d_in[1];
    const int*   dst    = (const int*)d_in[2];
    const float* W      = (const float*)d_in[3];
    const float* bias   = (const float*)d_in[4];
    const float* attn_w = (const float*)d_in[5];
    const float* attn_b = (const float*)d_in[6];
    const float* mask   = (const float*)d_in[7];
    float* out = (float*)d_out;

    int N = in_sizes[0] / DIM;   // 50000
    int E = in_sizes[1];         // 1600000

    static cudaStream_t s_side = nullptr;
    static cudaEvent_t ev_root = nullptr, ev_scat = nullptr;
    if (s_side == nullptr) {
        cudaStreamCreateWithFlags(&s_side, cudaStreamNonBlocking);
        cudaEventCreateWithFlags(&ev_root, cudaEventDisableTiming);
        cudaEventCreateWithFlags(&ev_scat, cudaEventDisableTiming);
    }

    int e4 = (E + 3) / 4;
    int foldBlocks = (N_NODES + 255) / 256;   // 196 blocks: blocks 0-15 fold, all zero deg

    // fork root so the side stream starts at t=0 within the graph
    cudaEventRecord(ev_root, 0);
    cudaStreamWaitEvent(s_side, ev_root, 0);

    // side: fold(+degzero, no deps) -> score -> scatterhist
    fold_kernel<<<foldBlocks, 256, 0, s_side>>>(W, mask, attn_w, bias);
    score_kernel<<<(N * 32 + 255) / 256, 256, 0, s_side>>>(feat, N);
    scatterhist_kernel<<<(e4 + 255) / 256, 256, 0, s_side>>>(src, dst, E);
    cudaEventRecord(ev_scat, s_side);

    // main: GEMM only (sigmoid fold inlined; h fp16)
    size_t smem = (size_t)(128 * 64 + 128 * 128) * sizeof(float);  // 96KB
    cudaFuncSetAttribute(gemm_kernel, cudaFuncAttributeMaxDynamicSharedMemorySize, (int)smem);
    gemm_kernel<<<(N + GB_M - 1) / GB_M, 128, smem>>>(feat, W, mask, bias, N);

    // join, then aggregate
    cudaStreamWaitEvent(0, ev_scat, 0);
    agg_kernel<<<(N * 32 + 255) / 256, 256>>>(out, attn_b, N);
}